// round 15
// baseline (speedup 1.0000x reference)
#include <cuda_runtime.h>
#include <cuda_bf16.h>
#include <cstdint>

#define NNODES 50000
#define CDIM   128
#define HMAX   4
#define EMAXT  450000   // 400000 edges + 50000 self loops
#define NSCANB 196      // ceil(50000/256)
#define NSTAGE 5

// ---------------- scratch (device globals: allocation-free) ----------------
__device__ __align__(16) float g_h[(long)NNODES * 512];   // post-GEMM features [N, H*C]
__device__ __align__(16) float g_buf1[NNODES * CDIM];     // layer-0 output
__device__ __align__(16) float g_buf2[NNODES * CDIM];     // layer-1 output
__device__ float g_s[NNODES * HMAX];             // per-node src scores
__device__ float g_d[NNODES * HMAX];             // per-node dst scores
__device__ float g_stats[2 * CDIM];              // BN: sum, sumsq
__device__ int   g_src[EMAXT];                   // decoded edge sources (int32)
__device__ int   g_dst[EMAXT];                   // decoded edge dests   (int32)
__device__ int   g_is64;                         // edge dtype flag
// CSR by destination
__device__ int   g_cnt[NNODES];
__device__ int   g_fill[NNODES];
__device__ int   g_off[NNODES + 1];
__device__ int   g_bsums[256];
__device__ int   g_bsumx[256];
__device__ int   g_csr_src[EMAXT];
// bf16 hi/lo split operands for tensor-core GEMM
__device__ __align__(16) __nv_bfloat16 g_abf[(long)NNODES * 512];  // [N, 2K] hi|lo (K<=256)
__device__ __align__(16) __nv_bfloat16 g_bbf[512 * 512];           // [M, 2K] transposed W

// ---------------- edge index dtype detection + decode ----------------
__global__ void detect_kernel(const int* __restrict__ raw) {
    __shared__ int nz;
    if (threadIdx.x == 0) nz = 0;
    __syncthreads();
    if (raw[2 * threadIdx.x + 1] != 0) atomicAdd(&nz, 1);
    __syncthreads();
    if (threadIdx.x == 0) g_is64 = (nz == 0) ? 1 : 0;
}

__global__ void decode_kernel(const int* __restrict__ raw, int E, int Etot) {
    int e = blockIdx.x * blockDim.x + threadIdx.x;
    if (e >= Etot) return;
    if (e < E) {
        if (g_is64) {
            g_src[e] = raw[2 * e];
            g_dst[e] = raw[2 * E + 2 * e];
        } else {
            g_src[e] = raw[e];
            g_dst[e] = raw[E + e];
        }
    } else {
        g_src[e] = e - E;
        g_dst[e] = e - E;
    }
}

// ---------------- CSR build (by dst) ----------------
__global__ void csr_zero_kernel() {
    int i = blockIdx.x * blockDim.x + threadIdx.x;
    if (i < NNODES) { g_cnt[i] = 0; g_fill[i] = 0; }
}

__global__ void csr_count_kernel(int Etot) {
    int e = blockIdx.x * blockDim.x + threadIdx.x;
    if (e < Etot) atomicAdd(&g_cnt[g_dst[e]], 1);
}

__global__ void csr_scan1_kernel() {
    __shared__ int sh[256];
    int t = threadIdx.x;
    int i = blockIdx.x * 256 + t;
    int v = (i < NNODES) ? g_cnt[i] : 0;
    sh[t] = v;
    __syncthreads();
#pragma unroll
    for (int d = 1; d < 256; d <<= 1) {
        int add = (t >= d) ? sh[t - d] : 0;
        __syncthreads();
        sh[t] += add;
        __syncthreads();
    }
    if (i < NNODES) g_off[i + 1] = sh[t];
    if (t == 255) g_bsums[blockIdx.x] = sh[255];
}

__global__ void csr_scan2_kernel() {
    __shared__ int sh[256];
    int t = threadIdx.x;
    int v = (t < NSCANB) ? g_bsums[t] : 0;
    sh[t] = v;
    __syncthreads();
#pragma unroll
    for (int d = 1; d < 256; d <<= 1) {
        int add = (t >= d) ? sh[t - d] : 0;
        __syncthreads();
        sh[t] += add;
        __syncthreads();
    }
    g_bsumx[t] = sh[t] - v;   // exclusive
}

__global__ void csr_fix_kernel() {
    int i = blockIdx.x * blockDim.x + threadIdx.x;
    if (i < NNODES) g_off[i + 1] += g_bsumx[i >> 8];
    if (i == 0) g_off[0] = 0;
}

__global__ void csr_place_kernel(int Etot) {
    int e = blockIdx.x * blockDim.x + threadIdx.x;
    if (e >= Etot) return;
    int d = g_dst[e];
    int pos = g_off[d] + atomicAdd(&g_fill[d], 1);
    g_csr_src[pos] = g_src[e];
}

// ---------------- fp32 -> bf16 hi/lo conversion (layer-0 input only) ----------------
// Also zeroes g_s/g_d score accumulators for the upcoming GEMM epilogue.
__global__ void convA_kernel(const float* __restrict__ A, __nv_bfloat16* __restrict__ out,
                             long total, int K) {
    long i = (long)blockIdx.x * blockDim.x + threadIdx.x;
    if (i >= total) return;
    if (i < NNODES * HMAX) { g_s[i] = 0.f; g_d[i] = 0.f; }
    int r = (int)(i / K);
    int c = (int)(i - (long)r * K);
    float x = A[i];
    __nv_bfloat16 hi = __float2bfloat16_rn(x);
    float rsd = x - __bfloat162float(hi);
    out[(long)r * 2 * K + c] = hi;
    out[(long)r * 2 * K + K + c] = __float2bfloat16_rn(rsd);
}

// W [K, M] row-major -> out [M, 2K] (transposed, hi|lo). Also zeroes g_stats.
__global__ void convB_kernel(const float* __restrict__ W, __nv_bfloat16* __restrict__ out,
                             int K, int M) {
    int i = blockIdx.x * blockDim.x + threadIdx.x;
    if (blockIdx.x == 0 && threadIdx.x < 2 * CDIM) g_stats[threadIdx.x] = 0.f;
    if (i >= K * M) return;
    int k = i / M, mc = i - k * M;
    float x = W[i];
    __nv_bfloat16 hi = __float2bfloat16_rn(x);
    float rsd = x - __bfloat162float(hi);
    out[(long)mc * 2 * K + k] = hi;
    out[(long)mc * 2 * K + K + k] = __float2bfloat16_rn(rsd);
}

// ---------------- helpers ----------------
__device__ __forceinline__ uint32_t smem_u32(const void* p) {
    uint32_t a;
    asm("{ .reg .u64 t; cvta.to.shared.u64 t, %1; cvt.u32.u64 %0, t; }" : "=r"(a) : "l"(p));
    return a;
}

// ---------------- HMMA GEMM: C[r,m] = A'[r,3K] @ B'[3K,m] (hi/lo split) ----------------
// Block 128x128, BK=32 bf16, 256 threads (8 warps, 4x2), warp tile 32x64.
// 5-stage cp.async pipeline, one barrier per chunk. Epilogue fuses attention
// scores s = C·a_src, d = C·a_dst (head = blockIdx.x since 128-col tile == head).
#define SPAD 40   // padded smem row stride (bf16 elems): conflict-free ldmatrix
#define TILEE (128 * SPAD)          // bf16 elems per matrix per stage
#define SMEM_BYTES (NSTAGE * 2 * TILEE * 2)
__global__ void __launch_bounds__(256)
mma_gemm_kernel(const __nv_bfloat16* __restrict__ Abf,
                const __nv_bfloat16* __restrict__ Bbf,
                float* __restrict__ C, int nrows, int K, int M,
                const float* __restrict__ a_src, const float* __restrict__ a_dst,
                int H) {
    extern __shared__ __align__(16) __nv_bfloat16 dsm[];
    const int tid = threadIdx.x;
    const int lane = tid & 31, wid = tid >> 5;
    const int wm = wid & 3, wn = wid >> 2;    // 4 warps along rows, 2 along cols
    const int row0 = blockIdx.y * 128, col0 = blockIdx.x * 128;
    const int K2 = 2 * K;
    const int cpp = K / 32;                   // chunks per phase
    const int total = 3 * cpp;

    float acc[2][8][4];
#pragma unroll
    for (int mi = 0; mi < 2; mi++)
#pragma unroll
        for (int ni = 0; ni < 8; ni++)
#pragma unroll
            for (int q = 0; q < 4; q++) acc[mi][ni][q] = 0.f;

    auto issue = [&](int gc) {
        int ph = gc / cpp, kc = gc - ph * cpp;
        int aoff = ((ph == 2) ? K : 0) + kc * 32;
        int boff = ((ph == 1) ? K : 0) + kc * 32;
        int st = gc % NSTAGE;
        __nv_bfloat16* sA = dsm + st * 2 * TILEE;
        __nv_bfloat16* sB = sA + TILEE;
#pragma unroll
        for (int u0 = 0; u0 < 2; u0++) {
            int u = u0 * 256 + tid;          // 512 units of 16B per tile
            int r = u >> 2, c8 = (u & 3) << 3;
            uint32_t da = smem_u32(&sA[r * SPAD + c8]);
            const void* ga = &Abf[(long)(row0 + r) * K2 + aoff + c8];
            int vsz = (row0 + r < nrows) ? 16 : 0;
            asm volatile("cp.async.cg.shared.global [%0], [%1], 16, %2;"
                         :: "r"(da), "l"(ga), "r"(vsz));
            uint32_t db = smem_u32(&sB[r * SPAD + c8]);
            const void* gb = &Bbf[(long)(col0 + r) * K2 + boff + c8];
            asm volatile("cp.async.cg.shared.global [%0], [%1], 16;"
                         :: "r"(db), "l"(gb));
        }
        asm volatile("cp.async.commit_group;");
    };

    for (int g = 0; g < NSTAGE - 1 && g < total; g++) issue(g);

#pragma unroll 1
    for (int gc = 0; gc < total; gc++) {
        int rem = total - 1 - gc;
        if (rem >= 3)      asm volatile("cp.async.wait_group 3;");
        else if (rem == 2) asm volatile("cp.async.wait_group 2;");
        else if (rem == 1) asm volatile("cp.async.wait_group 1;");
        else               asm volatile("cp.async.wait_group 0;");
        __syncthreads();
        if (gc + NSTAGE - 1 < total) issue(gc + NSTAGE - 1);

        int st = gc % NSTAGE;
        const __nv_bfloat16* sA = dsm + st * 2 * TILEE;
        const __nv_bfloat16* sB = sA + TILEE;
#pragma unroll
        for (int ks = 0; ks < 2; ks++) {
            int k0 = ks * 16;
            uint32_t af[2][4];
#pragma unroll
            for (int mi = 0; mi < 2; mi++) {
                int m0i = wm * 32 + mi * 16;
                uint32_t ad = smem_u32(
                    &sA[(m0i + (lane & 15)) * SPAD + k0 + ((lane >> 4) << 3)]);
                asm volatile("ldmatrix.sync.aligned.m8n8.x4.shared.b16 {%0,%1,%2,%3}, [%4];"
                             : "=r"(af[mi][0]), "=r"(af[mi][1]),
                               "=r"(af[mi][2]), "=r"(af[mi][3]) : "r"(ad));
            }
            uint32_t bfr[8][2];
#pragma unroll
            for (int p = 0; p < 4; p++) {
                int nb = wn * 64 + p * 16;
                uint32_t ad = smem_u32(
                    &sB[(nb + ((lane >> 4) << 3) + (lane & 7)) * SPAD
                        + k0 + (((lane >> 3) & 1) << 3)]);
                uint32_t r0, r1, r2, r3;
                asm volatile("ldmatrix.sync.aligned.m8n8.x4.shared.b16 {%0,%1,%2,%3}, [%4];"
                             : "=r"(r0), "=r"(r1), "=r"(r2), "=r"(r3) : "r"(ad));
                bfr[2 * p][0] = r0;  bfr[2 * p][1] = r1;
                bfr[2 * p + 1][0] = r2;  bfr[2 * p + 1][1] = r3;
            }
#pragma unroll
            for (int mi = 0; mi < 2; mi++)
#pragma unroll
                for (int ni = 0; ni < 8; ni++) {
                    asm volatile(
                        "mma.sync.aligned.m16n8k16.row.col.f32.bf16.bf16.f32 "
                        "{%0,%1,%2,%3}, {%4,%5,%6,%7}, {%8,%9}, {%0,%1,%2,%3};"
                        : "+f"(acc[mi][ni][0]), "+f"(acc[mi][ni][1]),
                          "+f"(acc[mi][ni][2]), "+f"(acc[mi][ni][3])
                        : "r"(af[mi][0]), "r"(af[mi][1]), "r"(af[mi][2]), "r"(af[mi][3]),
                          "r"(bfr[ni][0]), "r"(bfr[ni][1]));
                }
        }
    }

    // epilogue 1: write C. d0,d1 -> (row, col..col+1); d2,d3 -> (row+8, ...)
#pragma unroll
    for (int mi = 0; mi < 2; mi++)
#pragma unroll
        for (int ni = 0; ni < 8; ni++) {
            int row = row0 + wm * 32 + mi * 16 + (lane >> 2);
            int col = col0 + wn * 64 + ni * 8 + ((lane & 3) << 1);
            if (row < nrows)
                *(float2*)&C[(long)row * M + col] =
                    make_float2(acc[mi][ni][0], acc[mi][ni][1]);
            if (row + 8 < nrows)
                *(float2*)&C[(long)(row + 8) * M + col] =
                    make_float2(acc[mi][ni][2], acc[mi][ni][3]);
        }

    // epilogue 2: fused attention scores. head = blockIdx.x (128-col tile == head).
    {
        int h = blockIdx.x;
        float av[16], dvv[16];
#pragma unroll
        for (int ni = 0; ni < 8; ni++) {
#pragma unroll
            for (int q = 0; q < 2; q++) {
                int cc = wn * 64 + ni * 8 + ((lane & 3) << 1) + q;
                av[ni * 2 + q]  = a_src[h * CDIM + cc];
                dvv[ni * 2 + q] = a_dst[h * CDIM + cc];
            }
        }
        float sp[2][2] = {}, dp[2][2] = {};
#pragma unroll
        for (int mi = 0; mi < 2; mi++)
#pragma unroll
            for (int ni = 0; ni < 8; ni++) {
                sp[mi][0] = fmaf(av[2 * ni], acc[mi][ni][0],
                             fmaf(av[2 * ni + 1], acc[mi][ni][1], sp[mi][0]));
                sp[mi][1] = fmaf(av[2 * ni], acc[mi][ni][2],
                             fmaf(av[2 * ni + 1], acc[mi][ni][3], sp[mi][1]));
                dp[mi][0] = fmaf(dvv[2 * ni], acc[mi][ni][0],
                             fmaf(dvv[2 * ni + 1], acc[mi][ni][1], dp[mi][0]));
                dp[mi][1] = fmaf(dvv[2 * ni], acc[mi][ni][2],
                             fmaf(dvv[2 * ni + 1], acc[mi][ni][3], dp[mi][1]));
            }
#pragma unroll
        for (int mi = 0; mi < 2; mi++)
#pragma unroll
            for (int hf = 0; hf < 2; hf++) {
                float s = sp[mi][hf], d = dp[mi][hf];
                s += __shfl_xor_sync(0xffffffffu, s, 1);
                s += __shfl_xor_sync(0xffffffffu, s, 2);
                d += __shfl_xor_sync(0xffffffffu, d, 1);
                d += __shfl_xor_sync(0xffffffffu, d, 2);
                if ((lane & 3) == 0) {
                    int row = row0 + wm * 32 + mi * 16 + (lane >> 2) + hf * 8;
                    if (row < nrows) {
                        atomicAdd(&g_s[row * H + h], s);
                        atomicAdd(&g_d[row * H + h], d);
                    }
                }
            }
    }
}

// ---------------- fused attention: softmax + gather-aggregate + bias + BN stats ----
template<int H>
__global__ void attn_kernel(const float* __restrict__ hfeat, float* __restrict__ y,
                            const float* __restrict__ bias) {
    __shared__ float sm[2 * CDIM];
    int tid = threadIdx.x;
    sm[tid] = 0.f;
    __syncthreads();

    int w = (blockIdx.x * blockDim.x + tid) >> 5;
    int lane = tid & 31;
    if (w < NNODES) {
        int rs = g_off[w], re = g_off[w + 1];

        float dv[H];
#pragma unroll
        for (int h = 0; h < H; h++) dv[h] = g_d[w * H + h];

        float den[H];
#pragma unroll
        for (int h = 0; h < H; h++) den[h] = 0.f;
        for (int i = rs + lane; i < re; i += 32) {
            int src = g_csr_src[i];
#pragma unroll
            for (int h = 0; h < H; h++) {
                float e = g_s[src * H + h] + dv[h];
                e = e > 0.f ? e : 0.2f * e;
                den[h] += expf(e);
            }
        }
#pragma unroll
        for (int h = 0; h < H; h++) {
#pragma unroll
            for (int off = 16; off; off >>= 1)
                den[h] += __shfl_xor_sync(0xffffffffu, den[h], off);
        }
        float inv[H];
#pragma unroll
        for (int h = 0; h < H; h++) inv[h] = 1.f / den[h];

        float4 acc[H];
#pragma unroll
        for (int h = 0; h < H; h++) acc[h] = make_float4(0.f, 0.f, 0.f, 0.f);

        const int hh = (H > 1) ? (lane & 3) : 0;
        int i = rs;
        for (; i + 1 < re; i += 2) {
            int s0 = g_csr_src[i], s1 = g_csr_src[i + 1];
            float e0 = g_s[s0 * H + hh] + dv[hh];
            e0 = e0 > 0.f ? e0 : 0.2f * e0;
            float x0 = expf(e0);
            float e1 = g_s[s1 * H + hh] + dv[hh];
            e1 = e1 > 0.f ? e1 : 0.2f * e1;
            float x1 = expf(e1);
            const float4* p0 = (const float4*)&hfeat[(long)s0 * (H * CDIM)];
            const float4* p1 = (const float4*)&hfeat[(long)s1 * (H * CDIM)];
#pragma unroll
            for (int h = 0; h < H; h++) {
                float w0 = ((H > 1) ? __shfl_sync(0xffffffffu, x0, h) : x0) * inv[h];
                float w1 = ((H > 1) ? __shfl_sync(0xffffffffu, x1, h) : x1) * inv[h];
                float4 v0 = p0[h * 32 + lane];
                float4 v1 = p1[h * 32 + lane];
                acc[h].x = fmaf(w0, v0.x, fmaf(w1, v1.x, acc[h].x));
                acc[h].y = fmaf(w0, v0.y, fmaf(w1, v1.y, acc[h].y));
                acc[h].z = fmaf(w0, v0.z, fmaf(w1, v1.z, acc[h].z));
                acc[h].w = fmaf(w0, v0.w, fmaf(w1, v1.w, acc[h].w));
            }
        }
        if (i < re) {
            int s0 = g_csr_src[i];
            float e0 = g_s[s0 * H + hh] + dv[hh];
            e0 = e0 > 0.f ? e0 : 0.2f * e0;
            float x0 = expf(e0);
            const float4* p0 = (const float4*)&hfeat[(long)s0 * (H * CDIM)];
#pragma unroll
            for (int h = 0; h < H; h++) {
                float w0 = ((H > 1) ? __shfl_sync(0xffffffffu, x0, h) : x0) * inv[h];
                float4 v0 = p0[h * 32 + lane];
                acc[h].x = fmaf(w0, v0.x, acc[h].x);
                acc[h].y = fmaf(w0, v0.y, acc[h].y);
                acc[h].z = fmaf(w0, v0.z, acc[h].z);
                acc[h].w = fmaf(w0, v0.w, acc[h].w);
            }
        }

        float4 o = make_float4(0.f, 0.f, 0.f, 0.f);
#pragma unroll
        for (int h = 0; h < H; h++) {
            o.x += acc[h].x; o.y += acc[h].y; o.z += acc[h].z; o.w += acc[h].w;
        }
        const float invH = 1.f / (float)H;
        float4 b4 = ((const float4*)bias)[lane];
        o.x = fmaf(o.x, invH, b4.x);
        o.y = fmaf(o.y, invH, b4.y);
        o.z = fmaf(o.z, invH, b4.z);
        o.w = fmaf(o.w, invH, b4.w);
        ((float4*)&y[(long)w * CDIM])[lane] = o;

        // BN stats: block-level smem reduction
        int c = lane * 4;
        atomicAdd(&sm[c + 0], o.x);
        atomicAdd(&sm[c + 1], o.y);
        atomicAdd(&sm[c + 2], o.z);
        atomicAdd(&sm[c + 3], o.w);
        atomicAdd(&sm[CDIM + c + 0], o.x * o.x);
        atomicAdd(&sm[CDIM + c + 1], o.y * o.y);
        atomicAdd(&sm[CDIM + c + 2], o.z * o.z);
        atomicAdd(&sm[CDIM + c + 3], o.w * o.w);
    }
    __syncthreads();
    atomicAdd(&g_stats[tid], sm[tid]);
}

// ---------------- batch norm apply (scale/shift computed inline from g_stats) -------
// Optionally emits bf16 hi/lo for next layer (fused convA, K_next=128).
// Also zeroes g_s/g_d (score accumulators) for the next layer.
__global__ void norm_kernel(float* __restrict__ y, int relu, int emit,
                            __nv_bfloat16* __restrict__ abf,
                            const float* __restrict__ gamma,
                            const float* __restrict__ beta) {
    int i = blockIdx.x * blockDim.x + threadIdx.x;
    if (i >= NNODES * CDIM) return;
    if (i < NNODES * HMAX) { g_s[i] = 0.f; g_d[i] = 0.f; }
    int c = i & (CDIM - 1);
    float mean = g_stats[c] * (1.f / NNODES);
    float var  = g_stats[CDIM + c] * (1.f / NNODES) - mean * mean;
    float rstd = rsqrtf(var + 1e-5f);
    float sc = gamma[c] * rstd;
    float sh = beta[c] - mean * sc;
    float v = fmaf(y[i], sc, sh);
    if (relu) v = fmaxf(v, 0.f);
    y[i] = v;
    if (emit) {
        int r = i >> 7;
        __nv_bfloat16 hi = __float2bfloat16_rn(v);
        float rsd = v - __bfloat162float(hi);
        abf[(long)r * 256 + c] = hi;
        abf[(long)r * 256 + CDIM + c] = __float2bfloat16_rn(rsd);
    }
}

// ---------------- host ----------------
extern "C" void kernel_launch(void* const* d_in, const int* in_sizes, int n_in,
                              void* d_out, int out_size) {
    const float* x = (const float*)d_in[0];
    const int* ei_raw = (const int*)d_in[1];
    int E = in_sizes[1] / 2;
    int Etot = E + NNODES;

    float *hbuf, *buf1, *buf2;
    cudaGetSymbolAddress((void**)&hbuf, g_h);
    cudaGetSymbolAddress((void**)&buf1, g_buf1);
    cudaGetSymbolAddress((void**)&buf2, g_buf2);
    __nv_bfloat16 *abf, *bbf;
    cudaGetSymbolAddress((void**)&abf, g_abf);
    cudaGetSymbolAddress((void**)&bbf, g_bbf);

    static int smem_set = 0;
    if (!smem_set) {
        cudaFuncSetAttribute(mma_gemm_kernel,
                             cudaFuncAttributeMaxDynamicSharedMemorySize, SMEM_BYTES);
        smem_set = 1;
    }

    detect_kernel<<<1, 128>>>(ei_raw);
    decode_kernel<<<(Etot + 255) / 256, 256>>>(ei_raw, E, Etot);

    csr_zero_kernel<<<(NNODES + 255) / 256, 256>>>();
    csr_count_kernel<<<(Etot + 255) / 256, 256>>>(Etot);
    csr_scan1_kernel<<<NSCANB, 256>>>();
    csr_scan2_kernel<<<1, 256>>>();
    csr_fix_kernel<<<(NNODES + 255) / 256, 256>>>();
    csr_place_kernel<<<(Etot + 255) / 256, 256>>>(Etot);

    const int Ks[3] = {256, 128, 128};
    const int Hs[3] = {4, 4, 1};
    float* outs[3] = {buf1, buf2, (float*)d_out};

    for (int L = 0; L < 3; L++) {
        const float* W     = (const float*)d_in[2 + 6 * L];
        const float* asrc  = (const float*)d_in[3 + 6 * L];
        const float* adst  = (const float*)d_in[4 + 6 * L];
        const float* bias  = (const float*)d_in[5 + 6 * L];
        const float* gamma = (const float*)d_in[6 + 6 * L];
        const float* beta  = (const float*)d_in[7 + 6 * L];
        int K = Ks[L], H = Hs[L], M = H * CDIM;
        float* y = outs[L];

        if (L == 0) {
            long atot = (long)NNODES * K;
            convA_kernel<<<(int)((atot + 255) / 256), 256>>>(x, abf, atot, K);
        }
        convB_kernel<<<(K * M + 255) / 256, 256>>>(W, bbf, K, M);

        dim3 gg(M / 128, (NNODES + 127) / 128);
        mma_gemm_kernel<<<gg, 256, SMEM_BYTES>>>(abf, bbf, hbuf, NNODES, K, M,
                                                 asrc, adst, H);

        int ablocks = (NNODES * 32 + 255) / 256;
        if (H == 4) attn_kernel<4><<<ablocks, 256>>>(hbuf, y, bias);
        else        attn_kernel<1><<<ablocks, 256>>>(hbuf, y, bias);

        norm_kernel<<<(NNODES * CDIM + 255) / 256, 256>>>(y, (L < 2) ? 1 : 0,
                                                          (L < 2) ? 1 : 0, abf,
                                                          gamma, beta);
    }
}

// round 17
// speedup vs baseline: 1.0082x; 1.0082x over previous
#include <cuda_runtime.h>
#include <cuda_bf16.h>
#include <cstdint>

#define NNODES 50000
#define CDIM   128
#define HMAX   4
#define EMAXT  450000   // 400000 edges + 50000 self loops
#define NSCANB 196      // ceil(50000/256)
#define NSTAGE 3

// ---------------- scratch (device globals: allocation-free) ----------------
__device__ __align__(16) float g_h[(long)NNODES * 512];   // post-GEMM features [N, H*C]
__device__ __align__(16) float g_buf1[NNODES * CDIM];     // layer-0 output (unused sink)
__device__ __align__(16) float g_buf2[NNODES * CDIM];     // layer-1 output (unused sink)
__device__ float g_s[NNODES * HMAX];             // per-node src scores
__device__ float g_d[NNODES * HMAX];             // per-node dst scores
__device__ float g_stats[2 * CDIM];              // BN: sum, sumsq
__device__ int   g_src[EMAXT];                   // decoded edge sources (int32)
__device__ int   g_dst[EMAXT];                   // decoded edge dests   (int32)
__device__ int   g_is64;                         // edge dtype flag
// CSR by destination
__device__ int   g_cnt[NNODES];
__device__ int   g_fill[NNODES];
__device__ int   g_off[NNODES + 1];
__device__ int   g_bsums[256];
__device__ int   g_csr_src[EMAXT];
// bf16 hi/lo split operands for tensor-core GEMM
__device__ __align__(16) __nv_bfloat16 g_abf[(long)NNODES * 512];  // [N, 2K] hi|lo (K<=256)
__device__ __align__(16) __nv_bfloat16 g_bbf[512 * 512];           // [M, 2K] transposed W

// ---------------- edge index dtype detection + decode ----------------
__global__ void detect_kernel(const int* __restrict__ raw) {
    __shared__ int nz;
    if (threadIdx.x == 0) nz = 0;
    __syncthreads();
    if (raw[2 * threadIdx.x + 1] != 0) atomicAdd(&nz, 1);
    __syncthreads();
    if (threadIdx.x == 0) g_is64 = (nz == 0) ? 1 : 0;
}

// decode + zero CSR counters (merged csr_zero)
__global__ void decode_kernel(const int* __restrict__ raw, int E, int Etot) {
    int e = blockIdx.x * blockDim.x + threadIdx.x;
    if (e >= Etot) return;
    if (e < NNODES) { g_cnt[e] = 0; g_fill[e] = 0; }
    if (e < E) {
        if (g_is64) {
            g_src[e] = raw[2 * e];
            g_dst[e] = raw[2 * E + 2 * e];
        } else {
            g_src[e] = raw[e];
            g_dst[e] = raw[E + e];
        }
    } else {
        g_src[e] = e - E;
        g_dst[e] = e - E;
    }
}

// ---------------- CSR build (by dst) ----------------
__global__ void csr_count_kernel(int Etot) {
    int e = blockIdx.x * blockDim.x + threadIdx.x;
    if (e < Etot) atomicAdd(&g_cnt[g_dst[e]], 1);
}

__global__ void csr_scan1_kernel() {
    __shared__ int sh[256];
    int t = threadIdx.x;
    int i = blockIdx.x * 256 + t;
    int v = (i < NNODES) ? g_cnt[i] : 0;
    sh[t] = v;
    __syncthreads();
#pragma unroll
    for (int d = 1; d < 256; d <<= 1) {
        int add = (t >= d) ? sh[t - d] : 0;
        __syncthreads();
        sh[t] += add;
        __syncthreads();
    }
    if (i < NNODES) g_off[i + 1] = sh[t];
    if (t == 255) g_bsums[blockIdx.x] = sh[255];
}

// fused: exclusive scan of block sums + fixup of g_off (single block)
__global__ void csr_scan2fix_kernel() {
    __shared__ int sh[256];
    __shared__ int sx[256];
    int t = threadIdx.x;
    int v = (t < NSCANB) ? g_bsums[t] : 0;
    sh[t] = v;
    __syncthreads();
#pragma unroll
    for (int d = 1; d < 256; d <<= 1) {
        int add = (t >= d) ? sh[t - d] : 0;
        __syncthreads();
        sh[t] += add;
        __syncthreads();
    }
    sx[t] = sh[t] - v;   // exclusive
    __syncthreads();
    for (int i = t; i < NNODES; i += 256) g_off[i + 1] += sx[i >> 8];
    if (t == 0) g_off[0] = 0;
}

__global__ void csr_place_kernel(int Etot) {
    int e = blockIdx.x * blockDim.x + threadIdx.x;
    if (e >= Etot) return;
    int d = g_dst[e];
    int pos = g_off[d] + atomicAdd(&g_fill[d], 1);
    g_csr_src[pos] = g_src[e];
}

// ---------------- fp32 -> bf16 hi/lo conversion (layer-0 input only) ----------------
// Also zeroes g_s/g_d score accumulators for the upcoming GEMM epilogue.
__global__ void convA_kernel(const float* __restrict__ A, __nv_bfloat16* __restrict__ out,
                             long total, int K) {
    long i = (long)blockIdx.x * blockDim.x + threadIdx.x;
    if (i >= total) return;
    if (i < NNODES * HMAX) { g_s[i] = 0.f; g_d[i] = 0.f; }
    int r = (int)(i / K);
    int c = (int)(i - (long)r * K);
    float x = A[i];
    __nv_bfloat16 hi = __float2bfloat16_rn(x);
    float rsd = x - __bfloat162float(hi);
    out[(long)r * 2 * K + c] = hi;
    out[(long)r * 2 * K + K + c] = __float2bfloat16_rn(rsd);
}

// W [K, M] row-major -> out [M, 2K] (transposed, hi|lo). Also zeroes g_stats.
__global__ void convB_kernel(const float* __restrict__ W, __nv_bfloat16* __restrict__ out,
                             int K, int M) {
    int i = blockIdx.x * blockDim.x + threadIdx.x;
    if (blockIdx.x == 0 && threadIdx.x < 2 * CDIM) g_stats[threadIdx.x] = 0.f;
    if (i >= K * M) return;
    int k = i / M, mc = i - k * M;
    float x = W[i];
    __nv_bfloat16 hi = __float2bfloat16_rn(x);
    float rsd = x - __bfloat162float(hi);
    out[(long)mc * 2 * K + k] = hi;
    out[(long)mc * 2 * K + K + k] = __float2bfloat16_rn(rsd);
}

// ---------------- helpers ----------------
__device__ __forceinline__ uint32_t smem_u32(const void* p) {
    uint32_t a;
    asm("{ .reg .u64 t; cvta.to.shared.u64 t, %1; cvt.u32.u64 %0, t; }" : "=r"(a) : "l"(p));
    return a;
}

// ---------------- HMMA GEMM: C[r,m] = A'[r,3K] @ B'[3K,m] (hi/lo split) ----------------
// Block 128x128, BK=64 bf16, 256 threads (8 warps, 4x2), warp tile 32x64.
// 3-stage cp.async pipeline, one barrier per 64-K chunk. Epilogue fuses attention
// scores s = C·a_src, d = C·a_dst (head = blockIdx.x since 128-col tile == head).
#define SPAD 72   // padded smem row stride (bf16): 144B rows -> conflict-free ldmatrix
#define TILEE (128 * SPAD)          // bf16 elems per matrix per stage
#define SMEM_BYTES (NSTAGE * 2 * TILEE * 2)
__global__ void __launch_bounds__(256)
mma_gemm_kernel(const __nv_bfloat16* __restrict__ Abf,
                const __nv_bfloat16* __restrict__ Bbf,
                float* __restrict__ C, int nrows, int K, int M,
                const float* __restrict__ a_src, const float* __restrict__ a_dst,
                int H) {
    extern __shared__ __align__(16) __nv_bfloat16 dsm[];
    const int tid = threadIdx.x;
    const int lane = tid & 31, wid = tid >> 5;
    const int wm = wid & 3, wn = wid >> 2;    // 4 warps along rows, 2 along cols
    const int row0 = blockIdx.y * 128, col0 = blockIdx.x * 128;
    const int K2 = 2 * K;
    const int cpp = K / 64;                   // 64-K chunks per phase
    const int total = 3 * cpp;                // >= 3 always (K >= 128)

    float acc[2][8][4];
#pragma unroll
    for (int mi = 0; mi < 2; mi++)
#pragma unroll
        for (int ni = 0; ni < 8; ni++)
#pragma unroll
            for (int q = 0; q < 4; q++) acc[mi][ni][q] = 0.f;

    auto issue = [&](int gc) {
        int ph = gc / cpp, kc = gc - ph * cpp;
        int aoff = ((ph == 2) ? K : 0) + kc * 64;
        int boff = ((ph == 1) ? K : 0) + kc * 64;
        int st = gc % NSTAGE;
        __nv_bfloat16* sA = dsm + st * 2 * TILEE;
        __nv_bfloat16* sB = sA + TILEE;
#pragma unroll
        for (int u0 = 0; u0 < 4; u0++) {
            int u = u0 * 256 + tid;          // 1024 units of 16B per matrix
            int r = u >> 3, c8 = (u & 7) << 3;
            uint32_t da = smem_u32(&sA[r * SPAD + c8]);
            const void* ga = &Abf[(long)(row0 + r) * K2 + aoff + c8];
            int vsz = (row0 + r < nrows) ? 16 : 0;
            asm volatile("cp.async.cg.shared.global [%0], [%1], 16, %2;"
                         :: "r"(da), "l"(ga), "r"(vsz));
            uint32_t db = smem_u32(&sB[r * SPAD + c8]);
            const void* gb = &Bbf[(long)(col0 + r) * K2 + boff + c8];
            asm volatile("cp.async.cg.shared.global [%0], [%1], 16;"
                         :: "r"(db), "l"(gb));
        }
        asm volatile("cp.async.commit_group;");
    };

    issue(0);
    issue(1);

#pragma unroll 1
    for (int gc = 0; gc < total; gc++) {
        if (gc < total - 1) asm volatile("cp.async.wait_group 1;");
        else                asm volatile("cp.async.wait_group 0;");
        __syncthreads();
        if (gc + 2 < total) issue(gc + 2);

        int st = gc % NSTAGE;
        const __nv_bfloat16* sA = dsm + st * 2 * TILEE;
        const __nv_bfloat16* sB = sA + TILEE;
#pragma unroll
        for (int ks = 0; ks < 4; ks++) {
            int k0 = ks * 16;
            uint32_t af[2][4];
#pragma unroll
            for (int mi = 0; mi < 2; mi++) {
                int m0i = wm * 32 + mi * 16;
                uint32_t ad = smem_u32(
                    &sA[(m0i + (lane & 15)) * SPAD + k0 + ((lane >> 4) << 3)]);
                asm volatile("ldmatrix.sync.aligned.m8n8.x4.shared.b16 {%0,%1,%2,%3}, [%4];"
                             : "=r"(af[mi][0]), "=r"(af[mi][1]),
                               "=r"(af[mi][2]), "=r"(af[mi][3]) : "r"(ad));
            }
            uint32_t bfr[8][2];
#pragma unroll
            for (int p = 0; p < 4; p++) {
                int nb = wn * 64 + p * 16;
                uint32_t ad = smem_u32(
                    &sB[(nb + ((lane >> 4) << 3) + (lane & 7)) * SPAD
                        + k0 + (((lane >> 3) & 1) << 3)]);
                uint32_t r0, r1, r2, r3;
                asm volatile("ldmatrix.sync.aligned.m8n8.x4.shared.b16 {%0,%1,%2,%3}, [%4];"
                             : "=r"(r0), "=r"(r1), "=r"(r2), "=r"(r3) : "r"(ad));
                bfr[2 * p][0] = r0;  bfr[2 * p][1] = r1;
                bfr[2 * p + 1][0] = r2;  bfr[2 * p + 1][1] = r3;
            }
#pragma unroll
            for (int mi = 0; mi < 2; mi++)
#pragma unroll
                for (int ni = 0; ni < 8; ni++) {
                    asm volatile(
                        "mma.sync.aligned.m16n8k16.row.col.f32.bf16.bf16.f32 "
                        "{%0,%1,%2,%3}, {%4,%5,%6,%7}, {%8,%9}, {%0,%1,%2,%3};"
                        : "+f"(acc[mi][ni][0]), "+f"(acc[mi][ni][1]),
                          "+f"(acc[mi][ni][2]), "+f"(acc[mi][ni][3])
                        : "r"(af[mi][0]), "r"(af[mi][1]), "r"(af[mi][2]), "r"(af[mi][3]),
                          "r"(bfr[ni][0]), "r"(bfr[ni][1]));
                }
        }
    }

    // epilogue 1: write C. d0,d1 -> (row, col..col+1); d2,d3 -> (row+8, ...)
#pragma unroll
    for (int mi = 0; mi < 2; mi++)
#pragma unroll
        for (int ni = 0; ni < 8; ni++) {
            int row = row0 + wm * 32 + mi * 16 + (lane >> 2);
            int col = col0 + wn * 64 + ni * 8 + ((lane & 3) << 1);
            if (row < nrows)
                *(float2*)&C[(long)row * M + col] =
                    make_float2(acc[mi][ni][0], acc[mi][ni][1]);
            if (row + 8 < nrows)
                *(float2*)&C[(long)(row + 8) * M + col] =
                    make_float2(acc[mi][ni][2], acc[mi][ni][3]);
        }

    // epilogue 2: fused attention scores. head = blockIdx.x (128-col tile == head).
    {
        int h = blockIdx.x;
        float av[16], dvv[16];
#pragma unroll
        for (int ni = 0; ni < 8; ni++) {
#pragma unroll
            for (int q = 0; q < 2; q++) {
                int cc = wn * 64 + ni * 8 + ((lane & 3) << 1) + q;
                av[ni * 2 + q]  = a_src[h * CDIM + cc];
                dvv[ni * 2 + q] = a_dst[h * CDIM + cc];
            }
        }
        float sp[2][2] = {}, dp[2][2] = {};
#pragma unroll
        for (int mi = 0; mi < 2; mi++)
#pragma unroll
            for (int ni = 0; ni < 8; ni++) {
                sp[mi][0] = fmaf(av[2 * ni], acc[mi][ni][0],
                             fmaf(av[2 * ni + 1], acc[mi][ni][1], sp[mi][0]));
                sp[mi][1] = fmaf(av[2 * ni], acc[mi][ni][2],
                             fmaf(av[2 * ni + 1], acc[mi][ni][3], sp[mi][1]));
                dp[mi][0] = fmaf(dvv[2 * ni], acc[mi][ni][0],
                             fmaf(dvv[2 * ni + 1], acc[mi][ni][1], dp[mi][0]));
                dp[mi][1] = fmaf(dvv[2 * ni], acc[mi][ni][2],
                             fmaf(dvv[2 * ni + 1], acc[mi][ni][3], dp[mi][1]));
            }
#pragma unroll
        for (int mi = 0; mi < 2; mi++)
#pragma unroll
            for (int hf = 0; hf < 2; hf++) {
                float s = sp[mi][hf], d = dp[mi][hf];
                s += __shfl_xor_sync(0xffffffffu, s, 1);
                s += __shfl_xor_sync(0xffffffffu, s, 2);
                d += __shfl_xor_sync(0xffffffffu, d, 1);
                d += __shfl_xor_sync(0xffffffffu, d, 2);
                if ((lane & 3) == 0) {
                    int row = row0 + wm * 32 + mi * 16 + (lane >> 2) + hf * 8;
                    if (row < nrows) {
                        atomicAdd(&g_s[row * H + h], s);
                        atomicAdd(&g_d[row * H + h], d);
                    }
                }
            }
    }
}

// ---------------- fused attention: softmax + gather-aggregate + bias + BN stats ----
template<int H>
__global__ void attn_kernel(const float* __restrict__ hfeat, float* __restrict__ y,
                            const float* __restrict__ bias) {
    __shared__ float sm[2 * CDIM];
    int tid = threadIdx.x;
    sm[tid] = 0.f;
    __syncthreads();

    int w = (blockIdx.x * blockDim.x + tid) >> 5;
    int lane = tid & 31;
    if (w < NNODES) {
        int rs = g_off[w], re = g_off[w + 1];

        float dv[H];
#pragma unroll
        for (int h = 0; h < H; h++) dv[h] = g_d[w * H + h];

        float den[H];
#pragma unroll
        for (int h = 0; h < H; h++) den[h] = 0.f;
        for (int i = rs + lane; i < re; i += 32) {
            int src = g_csr_src[i];
#pragma unroll
            for (int h = 0; h < H; h++) {
                float e = g_s[src * H + h] + dv[h];
                e = e > 0.f ? e : 0.2f * e;
                den[h] += expf(e);
            }
        }
#pragma unroll
        for (int h = 0; h < H; h++) {
#pragma unroll
            for (int off = 16; off; off >>= 1)
                den[h] += __shfl_xor_sync(0xffffffffu, den[h], off);
        }
        float inv[H];
#pragma unroll
        for (int h = 0; h < H; h++) inv[h] = 1.f / den[h];

        float4 acc[H];
#pragma unroll
        for (int h = 0; h < H; h++) acc[h] = make_float4(0.f, 0.f, 0.f, 0.f);

        const int hh = (H > 1) ? (lane & 3) : 0;
        int i = rs;
        for (; i + 1 < re; i += 2) {
            int s0 = g_csr_src[i], s1 = g_csr_src[i + 1];
            float e0 = g_s[s0 * H + hh] + dv[hh];
            e0 = e0 > 0.f ? e0 : 0.2f * e0;
            float x0 = expf(e0);
            float e1 = g_s[s1 * H + hh] + dv[hh];
            e1 = e1 > 0.f ? e1 : 0.2f * e1;
            float x1 = expf(e1);
            const float4* p0 = (const float4*)&hfeat[(long)s0 * (H * CDIM)];
            const float4* p1 = (const float4*)&hfeat[(long)s1 * (H * CDIM)];
#pragma unroll
            for (int h = 0; h < H; h++) {
                float w0 = ((H > 1) ? __shfl_sync(0xffffffffu, x0, h) : x0) * inv[h];
                float w1 = ((H > 1) ? __shfl_sync(0xffffffffu, x1, h) : x1) * inv[h];
                float4 v0 = p0[h * 32 + lane];
                float4 v1 = p1[h * 32 + lane];
                acc[h].x = fmaf(w0, v0.x, fmaf(w1, v1.x, acc[h].x));
                acc[h].y = fmaf(w0, v0.y, fmaf(w1, v1.y, acc[h].y));
                acc[h].z = fmaf(w0, v0.z, fmaf(w1, v1.z, acc[h].z));
                acc[h].w = fmaf(w0, v0.w, fmaf(w1, v1.w, acc[h].w));
            }
        }
        if (i < re) {
            int s0 = g_csr_src[i];
            float e0 = g_s[s0 * H + hh] + dv[hh];
            e0 = e0 > 0.f ? e0 : 0.2f * e0;
            float x0 = expf(e0);
            const float4* p0 = (const float4*)&hfeat[(long)s0 * (H * CDIM)];
#pragma unroll
            for (int h = 0; h < H; h++) {
                float w0 = ((H > 1) ? __shfl_sync(0xffffffffu, x0, h) : x0) * inv[h];
                float4 v0 = p0[h * 32 + lane];
                acc[h].x = fmaf(w0, v0.x, acc[h].x);
                acc[h].y = fmaf(w0, v0.y, acc[h].y);
                acc[h].z = fmaf(w0, v0.z, acc[h].z);
                acc[h].w = fmaf(w0, v0.w, acc[h].w);
            }
        }

        float4 o = make_float4(0.f, 0.f, 0.f, 0.f);
#pragma unroll
        for (int h = 0; h < H; h++) {
            o.x += acc[h].x; o.y += acc[h].y; o.z += acc[h].z; o.w += acc[h].w;
        }
        const float invH = 1.f / (float)H;
        float4 b4 = ((const float4*)bias)[lane];
        o.x = fmaf(o.x, invH, b4.x);
        o.y = fmaf(o.y, invH, b4.y);
        o.z = fmaf(o.z, invH, b4.z);
        o.w = fmaf(o.w, invH, b4.w);
        ((float4*)&y[(long)w * CDIM])[lane] = o;

        // BN stats: block-level smem reduction
        int c = lane * 4;
        atomicAdd(&sm[c + 0], o.x);
        atomicAdd(&sm[c + 1], o.y);
        atomicAdd(&sm[c + 2], o.z);
        atomicAdd(&sm[c + 3], o.w);
        atomicAdd(&sm[CDIM + c + 0], o.x * o.x);
        atomicAdd(&sm[CDIM + c + 1], o.y * o.y);
        atomicAdd(&sm[CDIM + c + 2], o.z * o.z);
        atomicAdd(&sm[CDIM + c + 3], o.w * o.w);
    }
    __syncthreads();
    atomicAdd(&g_stats[tid], sm[tid]);
}

// ---------------- batch norm apply (scale/shift computed inline from g_stats) -------
// emit=1 (layers 0/1): writes ONLY the bf16 hi/lo operand for the next GEMM
// (the fp32 y buffer is never read again). emit=0 (layer 2): writes y.
// Also zeroes g_s/g_d (score accumulators) for the next layer.
__global__ void norm_kernel(float* __restrict__ y, int relu, int emit,
                            __nv_bfloat16* __restrict__ abf,
                            const float* __restrict__ gamma,
                            const float* __restrict__ beta) {
    int i = blockIdx.x * blockDim.x + threadIdx.x;
    if (i >= NNODES * CDIM) return;
    if (i < NNODES * HMAX) { g_s[i] = 0.f; g_d[i] = 0.f; }
    int c = i & (CDIM - 1);
    float mean = g_stats[c] * (1.f / NNODES);
    float var  = g_stats[CDIM + c] * (1.f / NNODES) - mean * mean;
    float rstd = rsqrtf(var + 1e-5f);
    float sc = gamma[c] * rstd;
    float sh = beta[c] - mean * sc;
    float v = fmaf(y[i], sc, sh);
    if (relu) v = fmaxf(v, 0.f);
    if (emit) {
        int r = i >> 7;
        __nv_bfloat16 hi = __float2bfloat16_rn(v);
        float rsd = v - __bfloat162float(hi);
        abf[(long)r * 256 + c] = hi;
        abf[(long)r * 256 + CDIM + c] = __float2bfloat16_rn(rsd);
    } else {
        y[i] = v;
    }
}

// ---------------- host ----------------
extern "C" void kernel_launch(void* const* d_in, const int* in_sizes, int n_in,
                              void* d_out, int out_size) {
    const float* x = (const float*)d_in[0];
    const int* ei_raw = (const int*)d_in[1];
    int E = in_sizes[1] / 2;
    int Etot = E + NNODES;

    float *hbuf, *buf1, *buf2;
    cudaGetSymbolAddress((void**)&hbuf, g_h);
    cudaGetSymbolAddress((void**)&buf1, g_buf1);
    cudaGetSymbolAddress((void**)&buf2, g_buf2);
    __nv_bfloat16 *abf, *bbf;
    cudaGetSymbolAddress((void**)&abf, g_abf);
    cudaGetSymbolAddress((void**)&bbf, g_bbf);

    static int smem_set = 0;
    if (!smem_set) {
        cudaFuncSetAttribute(mma_gemm_kernel,
                             cudaFuncAttributeMaxDynamicSharedMemorySize, SMEM_BYTES);
        smem_set = 1;
    }

    detect_kernel<<<1, 128>>>(ei_raw);
    decode_kernel<<<(Etot + 255) / 256, 256>>>(ei_raw, E, Etot);

    csr_count_kernel<<<(Etot + 255) / 256, 256>>>(Etot);
    csr_scan1_kernel<<<NSCANB, 256>>>();
    csr_scan2fix_kernel<<<1, 256>>>();
    csr_place_kernel<<<(Etot + 255) / 256, 256>>>(Etot);

    const int Ks[3] = {256, 128, 128};
    const int Hs[3] = {4, 4, 1};
    float* outs[3] = {buf1, buf2, (float*)d_out};

    for (int L = 0; L < 3; L++) {
        const float* W     = (const float*)d_in[2 + 6 * L];
        const float* asrc  = (const float*)d_in[3 + 6 * L];
        const float* adst  = (const float*)d_in[4 + 6 * L];
        const float* bias  = (const float*)d_in[5 + 6 * L];
        const float* gamma = (const float*)d_in[6 + 6 * L];
        const float* beta  = (const float*)d_in[7 + 6 * L];
        int K = Ks[L], H = Hs[L], M = H * CDIM;
        float* y = outs[L];

        if (L == 0) {
            long atot = (long)NNODES * K;
            convA_kernel<<<(int)((atot + 255) / 256), 256>>>(x, abf, atot, K);
        }
        convB_kernel<<<(K * M + 255) / 256, 256>>>(W, bbf, K, M);

        dim3 gg(M / 128, (NNODES + 127) / 128);
        mma_gemm_kernel<<<gg, 256, SMEM_BYTES>>>(abf, bbf, hbuf, NNODES, K, M,
                                                 asrc, adst, H);

        int ablocks = (NNODES * 32 + 255) / 256;
        if (H == 4) attn_kernel<4><<<ablocks, 256>>>(hbuf, y, bias);
        else        attn_kernel<1><<<ablocks, 256>>>(hbuf, y, bias);

        norm_kernel<<<(NNODES * CDIM + 255) / 256, 256>>>(y, (L < 2) ? 1 : 0,
                                                          (L < 2) ? 1 : 0, abf,
                                                          gamma, beta);
    }
}